// round 15
// baseline (speedup 1.0000x reference)
#include <cuda_runtime.h>
#include <cuda_bf16.h>
#include <cstdint>

// ---------------------------------------------------------------------------
// SubGraph: 3x (MLP -> gather/scatter-max -> concat) -> cluster max-pool ->
// column-wise L2 normalization.
// N=50000, E=800000, C0=64, H=64, NC=2500. Channels 64->128->256->512.
// Round 15: round-14 base (354.2us) + matmul1 K-split: h-half chunks run as
// mlp_head on the side stream concurrent with agg (partial f32 accumulators
// in g_tp); mlp_tail resumes from g_tp. Round-8-proven 6-event topology.
// ---------------------------------------------------------------------------

// Static scratch (no allocations allowed)
__device__ __align__(16) float g_X1[50000 * 128];
__device__ __align__(16) float g_X2[50000 * 256];
__device__ __align__(16) float g_X3[50000 * 512];
__device__ __align__(16) float g_pool[2500 * 512];
__device__ __align__(16) float g_tp[50000 * 64];   // partial matmul1 accumulators

// packed weights for layers 1/2
__device__ __align__(16) uint2 g_pw1_1[64 * 64];
__device__ __align__(16) uint2 g_pw1_2[128 * 64];
__device__ __align__(16) uint2 g_pw2_1[64 * 64];
__device__ __align__(16) uint2 g_pw2_2[128 * 64];

__device__ int g_cnt[50000];
__device__ int g_off[50001];
__device__ int g_cur[50000];
__device__ int g_csr[800000];

__device__ int g_ccnt[2500];
__device__ int g_coff[2501];
__device__ int g_ccur[2500];
__device__ int g_ccsr[50000];

__device__ __forceinline__ float4 max4(float4 a, float4 b) {
    return make_float4(fmaxf(a.x, b.x), fmaxf(a.y, b.y),
                       fmaxf(a.z, b.z), fmaxf(a.w, b.w));
}

// ---------------------------------------------------------------------------
// bf16 split helpers + mma
// ---------------------------------------------------------------------------
__device__ __forceinline__ uint2 split_pack2(float x0, float x1)
{
    __nv_bfloat16 h0 = __float2bfloat16_rn(x0);
    __nv_bfloat16 h1 = __float2bfloat16_rn(x1);
    float f0 = __bfloat162float(h0), f1 = __bfloat162float(h1);
    __nv_bfloat16 l0 = __float2bfloat16_rn(x0 - f0);
    __nv_bfloat16 l1 = __float2bfloat16_rn(x1 - f1);
    uint2 r;
    r.x = ((unsigned)__bfloat16_as_ushort(h1) << 16) | (unsigned)__bfloat16_as_ushort(h0);
    r.y = ((unsigned)__bfloat16_as_ushort(l1) << 16) | (unsigned)__bfloat16_as_ushort(l0);
    return r;
}

__device__ __forceinline__ void mma16816(float* c,
    unsigned a0, unsigned a1, unsigned a2, unsigned a3,
    unsigned b0, unsigned b1)
{
    asm volatile(
        "mma.sync.aligned.m16n8k16.row.col.f32.bf16.bf16.f32 "
        "{%0,%1,%2,%3}, {%4,%5,%6,%7}, {%8,%9}, {%0,%1,%2,%3};"
        : "+f"(c[0]), "+f"(c[1]), "+f"(c[2]), "+f"(c[3])
        : "r"(a0), "r"(a1), "r"(a2), "r"(a3), "r"(b0), "r"(b1));
}

// ---------------------------------------------------------------------------
// Weight pre-pack kernels (side stream; layers 1/2 only)
// ---------------------------------------------------------------------------
__global__ void pack_w1_kernel(const float* __restrict__ w, uint2* __restrict__ out, int K)
{
    int idx = blockIdx.x * 256 + threadIdx.x;
    if (idx >= (K / 2) * 64) return;
    int kw = idx >> 6, nn = idx & 63;
    out[idx] = split_pack2(__ldg(&w[(long)(2 * kw) * 64 + nn]),
                           __ldg(&w[(long)(2 * kw + 1) * 64 + nn]));
}

__global__ void pack_w2_kernel(const float* __restrict__ w, uint2* __restrict__ out, int C)
{
    int idx = blockIdx.x * 256 + threadIdx.x;
    if (idx >= C * 32) return;
    int cc = idx >> 11;
    int kw = (idx >> 6) & 31;
    int nn = idx & 63;
    out[idx] = split_pack2(__ldg(&w[(long)(2 * kw) * C + cc * 64 + nn]),
                           __ldg(&w[(long)(2 * kw + 1) * C + cc * 64 + nn]));
}

// ---------------------------------------------------------------------------
// CSR build
// ---------------------------------------------------------------------------
__global__ void hist_kernel(const int* __restrict__ idx, int* __restrict__ cnt, int m)
{
    int i = blockIdx.x * blockDim.x + threadIdx.x;
    if (i < m) atomicAdd(&cnt[__ldg(idx + i)], 1);
}

__global__ void scan_kernel(const int* __restrict__ cnt, int* __restrict__ off,
                            int* __restrict__ cur, int n)
{
    __shared__ int sums[1024];
    int tid = threadIdx.x;
    int chunk = (n + 1023) >> 10;
    int start = tid * chunk;
    int lim = min(start + chunk, n);
    int s = 0;
    for (int i = start; i < lim; ++i) s += cnt[i];
    sums[tid] = s;
    __syncthreads();
    for (int d = 1; d < 1024; d <<= 1) {
        int v = (tid >= d) ? sums[tid - d] : 0;
        __syncthreads();
        sums[tid] += v;
        __syncthreads();
    }
    int run = (tid == 0) ? 0 : sums[tid - 1];
    for (int i = start; i < lim; ++i) {
        off[i] = run; cur[i] = run;
        run += cnt[i];
    }
    if (tid == 1023) off[n] = sums[1023];
}

__global__ void fill_edge_kernel(const int* __restrict__ src, const int* __restrict__ dst,
                                 int* __restrict__ cur, int* __restrict__ csr, int E)
{
    int e = blockIdx.x * blockDim.x + threadIdx.x;
    if (e >= E) return;
    int pos = atomicAdd(&cur[__ldg(dst + e)], 1);
    csr[pos] = __ldg(src + e);
}

__global__ void fill_node_kernel(const int* __restrict__ cl, int* __restrict__ ccur,
                                 int* __restrict__ ccsr, int n)
{
    int i = blockIdx.x * blockDim.x + threadIdx.x;
    if (i >= n) return;
    int pos = atomicAdd(&ccur[__ldg(cl + i)], 1);
    ccsr[pos] = i;
}

// ---------------------------------------------------------------------------
// Shared MLP machinery: 256 thr = 8 warps (4 row x 2 col), tile 128x64.
// Smem 55296 B, 3 CTAs/SM.
// ---------------------------------------------------------------------------

// matmul1 chunk step: stage A (+B) and mma, for chunk kc.
template<int C, bool WPACK>
__device__ __forceinline__ void m1_chunk(
    const float* __restrict__ X, const void* __restrict__ w1v,
    unsigned* sA_hi, unsigned* sA_lo, unsigned* sB_hi, unsigned* sB_lo,
    float c[2][4][4], int kc, int rowBase, int n,
    int tid, int g, int t4, int warpRow, int warpCol, int nn, int k0)
{
    constexpr int SA = 20, SB = 36;
    __syncthreads();
#pragma unroll
    for (int it = 0; it < 8; ++it) {
        int idx = tid + it * 256;
        int r = idx >> 4, kw = idx & 15;
        int row = rowBase + r;
        float2 v = make_float2(0.f, 0.f);
        if (row < n) v = *(const float2*)&X[(long)row * C + kc * 32 + kw * 2];
        uint2 p = split_pack2(v.x, v.y);
        sA_hi[r * SA + kw] = p.x; sA_lo[r * SA + kw] = p.y;
    }
    if (WPACK) {
        const uint2* pw1 = (const uint2*)w1v;
#pragma unroll
        for (int i = 0; i < 4; ++i) {
            int kw = k0 + i * 4;
            uint2 v = __ldg(&pw1[((long)kc * 16 + kw) * 64 + nn]);
            sB_hi[nn * SB + kw] = v.x; sB_lo[nn * SB + kw] = v.y;
        }
    } else {
        const float* w1 = (const float*)w1v;
#pragma unroll
        for (int i = 0; i < 4; ++i) {
            int kw = k0 + i * 4;
            int k = kc * 32 + kw * 2;
            uint2 v = split_pack2(__ldg(&w1[(long)k * 64 + nn]),
                                  __ldg(&w1[(long)(k + 1) * 64 + nn]));
            sB_hi[nn * SB + kw] = v.x; sB_lo[nn * SB + kw] = v.y;
        }
    }
    __syncthreads();

#pragma unroll
    for (int ks = 0; ks < 2; ++ks) {
        int kw0 = ks * 8;
        unsigned ah[2][4], al[2][4];
#pragma unroll
        for (int mt = 0; mt < 2; ++mt) {
            int r0 = warpRow * 32 + mt * 16;
            ah[mt][0] = sA_hi[(r0 + g) * SA + kw0 + t4];
            ah[mt][1] = sA_hi[(r0 + g + 8) * SA + kw0 + t4];
            ah[mt][2] = sA_hi[(r0 + g) * SA + kw0 + 4 + t4];
            ah[mt][3] = sA_hi[(r0 + g + 8) * SA + kw0 + 4 + t4];
            al[mt][0] = sA_lo[(r0 + g) * SA + kw0 + t4];
            al[mt][1] = sA_lo[(r0 + g + 8) * SA + kw0 + t4];
            al[mt][2] = sA_lo[(r0 + g) * SA + kw0 + 4 + t4];
            al[mt][3] = sA_lo[(r0 + g + 8) * SA + kw0 + 4 + t4];
        }
#pragma unroll
        for (int nt = 0; nt < 4; ++nt) {
            int nb_ = warpCol * 32 + nt * 8;
            unsigned bh0 = sB_hi[(nb_ + g) * SB + kw0 + t4];
            unsigned bh1 = sB_hi[(nb_ + g) * SB + kw0 + 4 + t4];
            unsigned bl0 = sB_lo[(nb_ + g) * SB + kw0 + t4];
            unsigned bl1 = sB_lo[(nb_ + g) * SB + kw0 + 4 + t4];
#pragma unroll
            for (int mt = 0; mt < 2; ++mt) {
                mma16816(c[mt][nt], ah[mt][0], ah[mt][1], ah[mt][2], ah[mt][3], bh0, bh1);
                mma16816(c[mt][nt], ah[mt][0], ah[mt][1], ah[mt][2], ah[mt][3], bl0, bl1);
                mma16816(c[mt][nt], al[mt][0], al[mt][1], al[mt][2], al[mt][3], bh0, bh1);
            }
        }
    }
}

// head: accum over chunks [0, KEND) of matmul1; store f32 accumulators to tp.
template<int C, bool WPACK, int KEND>
__global__ void __launch_bounds__(256, 3) mlp_mma_head(
    const float* __restrict__ X, const void* __restrict__ w1v,
    float* __restrict__ tp, int n)
{
    constexpr int ST = 36, SB = 36;
    extern __shared__ unsigned smem[];
    unsigned* sA_hi = smem;
    unsigned* sA_lo = sA_hi + 128 * ST;
    unsigned* sB_hi = sA_lo + 128 * ST;
    unsigned* sB_lo = sB_hi + 64 * SB;

    const int tid = threadIdx.x;
    const int wid = tid >> 5, lane = tid & 31;
    const int g = lane >> 2, t4 = lane & 3;
    const int warpRow = wid >> 1, warpCol = wid & 1;
    const int rowBase = blockIdx.x * 128;
    const int nn = tid & 63, k0 = tid >> 6;

    float c[2][4][4];
#pragma unroll
    for (int a = 0; a < 2; ++a)
#pragma unroll
        for (int b = 0; b < 4; ++b)
#pragma unroll
            for (int d = 0; d < 4; ++d) c[a][b][d] = 0.f;

    for (int kc = 0; kc < KEND; ++kc)
        m1_chunk<C, WPACK>(X, w1v, sA_hi, sA_lo, sB_hi, sB_lo, c,
                           kc, rowBase, n, tid, g, t4, warpRow, warpCol, nn, k0);

    // store accumulators (fragment layout) to tp[row*64 + col]
#pragma unroll
    for (int mt = 0; mt < 2; ++mt) {
#pragma unroll
        for (int nt = 0; nt < 4; ++nt) {
            int j = warpCol * 32 + nt * 8 + t4 * 2;
            int r0 = rowBase + warpRow * 32 + mt * 16 + g;
            if (r0 < n)
                *(float2*)&tp[(long)r0 * 64 + j] = make_float2(c[mt][nt][0], c[mt][nt][1]);
            if (r0 + 8 < n)
                *(float2*)&tp[(long)(r0 + 8) * 64 + j] = make_float2(c[mt][nt][2], c[mt][nt][3]);
        }
    }
}

// full/tail MLP: optionally init accum from tp, run chunks [KSTART, C/32),
// then bias+relu+repack and matmul2.
template<int C, bool WPACK, int KSTART, bool HAS_TP>
__global__ void __launch_bounds__(256, 3) mlp_mma_kernel(
    const float* __restrict__ X, const float* __restrict__ tp,
    const void* __restrict__ w1v, const float* __restrict__ b1,
    const void* __restrict__ w2v, const float* __restrict__ b2,
    float* __restrict__ Y, int n)
{
    constexpr int LD_OUT = 2 * C;
    constexpr int ST = 36, SB = 36;

    extern __shared__ unsigned smem[];
    unsigned* sA_hi = smem;
    unsigned* sA_lo = sA_hi + 128 * ST;
    unsigned* sB_hi = sA_lo + 128 * ST;
    unsigned* sB_lo = sB_hi + 64 * SB;

    const int tid = threadIdx.x;
    const int wid = tid >> 5, lane = tid & 31;
    const int g = lane >> 2, t4 = lane & 3;
    const int warpRow = wid >> 1, warpCol = wid & 1;
    const int rowBase = blockIdx.x * 128;
    const int nn = tid & 63, k0 = tid >> 6;

    float c[2][4][4];
    if (HAS_TP) {
#pragma unroll
        for (int mt = 0; mt < 2; ++mt) {
#pragma unroll
            for (int nt = 0; nt < 4; ++nt) {
                int j = warpCol * 32 + nt * 8 + t4 * 2;
                int r0 = rowBase + warpRow * 32 + mt * 16 + g;
                float2 p0 = make_float2(0.f, 0.f), p1 = p0;
                if (r0 < n)     p0 = *(const float2*)&tp[(long)r0 * 64 + j];
                if (r0 + 8 < n) p1 = *(const float2*)&tp[(long)(r0 + 8) * 64 + j];
                c[mt][nt][0] = p0.x; c[mt][nt][1] = p0.y;
                c[mt][nt][2] = p1.x; c[mt][nt][3] = p1.y;
            }
        }
    } else {
#pragma unroll
        for (int a = 0; a < 2; ++a)
#pragma unroll
            for (int b = 0; b < 4; ++b)
#pragma unroll
                for (int d = 0; d < 4; ++d) c[a][b][d] = 0.f;
    }

    for (int kc = KSTART; kc < C / 32; ++kc)
        m1_chunk<C, WPACK>(X, w1v, sA_hi, sA_lo, sB_hi, sB_lo, c,
                           kc, rowBase, n, tid, g, t4, warpRow, warpCol, nn, k0);

    __syncthreads();   // all A/B reads done; safe to overwrite as t

    // ---- bias + relu; repack t (bf16 hi/lo) into sA with stride ST ----
#pragma unroll
    for (int mt = 0; mt < 2; ++mt) {
#pragma unroll
        for (int nt = 0; nt < 4; ++nt) {
            int j = warpCol * 32 + nt * 8 + t4 * 2;
            float2 bb = *(const float2*)&b1[j];
            float v0 = fmaxf(c[mt][nt][0] + bb.x, 0.f);
            float v1 = fmaxf(c[mt][nt][1] + bb.y, 0.f);
            float v2 = fmaxf(c[mt][nt][2] + bb.x, 0.f);
            float v3 = fmaxf(c[mt][nt][3] + bb.y, 0.f);
            int r0 = warpRow * 32 + mt * 16 + g;
            int wc = warpCol * 16 + nt * 4 + t4;
            uint2 p0 = split_pack2(v0, v1);
            sA_hi[r0 * ST + wc] = p0.x; sA_lo[r0 * ST + wc] = p0.y;
            uint2 p1 = split_pack2(v2, v3);
            sA_hi[(r0 + 8) * ST + wc] = p1.x; sA_lo[(r0 + 8) * ST + wc] = p1.y;
        }
    }

    // ---- matmul2: Y = t @ w2 + b2, 64-col output slices ----
    for (int cc = 0; cc < C / 64; ++cc) {
        __syncthreads();
        if (WPACK) {
            const uint2* pw2 = (const uint2*)w2v;
#pragma unroll
            for (int i = 0; i < 8; ++i) {
                int kw = k0 + i * 4;
                uint2 v = __ldg(&pw2[((long)cc * 32 + kw) * 64 + nn]);
                sB_hi[nn * SB + kw] = v.x; sB_lo[nn * SB + kw] = v.y;
            }
        } else {
            const float* w2 = (const float*)w2v;
#pragma unroll
            for (int i = 0; i < 8; ++i) {
                int kw = k0 + i * 4;
                int k = kw * 2;
                uint2 v = split_pack2(__ldg(&w2[(long)k * C + cc * 64 + nn]),
                                      __ldg(&w2[(long)(k + 1) * C + cc * 64 + nn]));
                sB_hi[nn * SB + kw] = v.x; sB_lo[nn * SB + kw] = v.y;
            }
        }
        __syncthreads();

        float c2[2][4][4];
#pragma unroll
        for (int a = 0; a < 2; ++a)
#pragma unroll
            for (int b = 0; b < 4; ++b)
#pragma unroll
                for (int d = 0; d < 4; ++d) c2[a][b][d] = 0.f;

#pragma unroll
        for (int ks = 0; ks < 4; ++ks) {
            int kw0 = ks * 8;
            unsigned ah[2][4], al[2][4];
#pragma unroll
            for (int mt = 0; mt < 2; ++mt) {
                int r0 = warpRow * 32 + mt * 16;
                ah[mt][0] = sA_hi[(r0 + g) * ST + kw0 + t4];
                ah[mt][1] = sA_hi[(r0 + g + 8) * ST + kw0 + t4];
                ah[mt][2] = sA_hi[(r0 + g) * ST + kw0 + 4 + t4];
                ah[mt][3] = sA_hi[(r0 + g + 8) * ST + kw0 + 4 + t4];
                al[mt][0] = sA_lo[(r0 + g) * ST + kw0 + t4];
                al[mt][1] = sA_lo[(r0 + g + 8) * ST + kw0 + t4];
                al[mt][2] = sA_lo[(r0 + g) * ST + kw0 + 4 + t4];
                al[mt][3] = sA_lo[(r0 + g + 8) * ST + kw0 + 4 + t4];
            }
#pragma unroll
            for (int nt = 0; nt < 4; ++nt) {
                int nb_ = warpCol * 32 + nt * 8;
                unsigned bh0 = sB_hi[(nb_ + g) * SB + kw0 + t4];
                unsigned bh1 = sB_hi[(nb_ + g) * SB + kw0 + 4 + t4];
                unsigned bl0 = sB_lo[(nb_ + g) * SB + kw0 + t4];
                unsigned bl1 = sB_lo[(nb_ + g) * SB + kw0 + 4 + t4];
#pragma unroll
                for (int mt = 0; mt < 2; ++mt) {
                    mma16816(c2[mt][nt], ah[mt][0], ah[mt][1], ah[mt][2], ah[mt][3], bh0, bh1);
                    mma16816(c2[mt][nt], ah[mt][0], ah[mt][1], ah[mt][2], ah[mt][3], bl0, bl1);
                    mma16816(c2[mt][nt], al[mt][0], al[mt][1], al[mt][2], al[mt][3], bh0, bh1);
                }
            }
        }

        // + b2, store f32 to Y
#pragma unroll
        for (int mt = 0; mt < 2; ++mt) {
#pragma unroll
            for (int nt = 0; nt < 4; ++nt) {
                int j = cc * 64 + warpCol * 32 + nt * 8 + t4 * 2;
                float2 bb = *(const float2*)&b2[j];
                int r0 = rowBase + warpRow * 32 + mt * 16 + g;
                if (r0 < n)
                    *(float2*)&Y[(long)r0 * LD_OUT + j] =
                        make_float2(c2[mt][nt][0] + bb.x, c2[mt][nt][1] + bb.y);
                if (r0 + 8 < n)
                    *(float2*)&Y[(long)(r0 + 8) * LD_OUT + j] =
                        make_float2(c2[mt][nt][2] + bb.x, c2[mt][nt][3] + bb.y);
            }
        }
    }
}

// ---------------------------------------------------------------------------
// CSR gather-max aggregation
// ---------------------------------------------------------------------------
template<int C>
__global__ void __launch_bounds__(256) agg_kernel(
    float* __restrict__ Xn,
    const int* __restrict__ csr, const int* __restrict__ off, int n)
{
    constexpr int LD  = 2 * C;
    constexpr int V   = C / 4;
    constexpr int LPE = (V < 32) ? V : 32;
    constexpr int EPW = 32 / LPE;
    constexpr int NV  = V / LPE;

    int gwarp = (int)((blockIdx.x * 256u + threadIdx.x) >> 5);
    int lane  = threadIdx.x & 31;
    int node  = gwarp * EPW + (EPW > 1 ? lane / LPE : 0);
    if (node >= n) return;
    int li = lane % LPE;

    int beg = off[node], end = off[node + 1];

    float4 m[NV];
#pragma unroll
    for (int v = 0; v < NV; ++v)
        m[v] = make_float4(-INFINITY, -INFINITY, -INFINITY, -INFINITY);

    int e = beg;
    for (; e + 3 < end; e += 4) {
        int s0 = __ldg(csr + e), s1 = __ldg(csr + e + 1);
        int s2 = __ldg(csr + e + 2), s3 = __ldg(csr + e + 3);
        const float4* h0 = (const float4*)(Xn + (long)s0 * LD) + li;
        const float4* h1 = (const float4*)(Xn + (long)s1 * LD) + li;
        const float4* h2 = (const float4*)(Xn + (long)s2 * LD) + li;
        const float4* h3 = (const float4*)(Xn + (long)s3 * LD) + li;
#pragma unroll
        for (int v = 0; v < NV; ++v) {
            float4 a = h0[v * LPE];
            float4 b = h1[v * LPE];
            float4 c = h2[v * LPE];
            float4 d = h3[v * LPE];
            m[v] = max4(m[v], max4(max4(a, b), max4(c, d)));
        }
    }
    for (; e < end; ++e) {
        const float4* h0 = (const float4*)(Xn + (long)__ldg(csr + e) * LD) + li;
#pragma unroll
        for (int v = 0; v < NV; ++v)
            m[v] = max4(m[v], h0[v * LPE]);
    }

    float4* ap = (float4*)(Xn + (long)node * LD + C);
    if (beg == end) {
#pragma unroll
        for (int v = 0; v < NV; ++v)
            ap[li + v * LPE] = make_float4(0.f, 0.f, 0.f, 0.f);
    } else {
#pragma unroll
        for (int v = 0; v < NV; ++v)
            ap[li + v * LPE] = m[v];
    }
}

// ---------------------------------------------------------------------------
// Cluster max-pool via CSR
// ---------------------------------------------------------------------------
__global__ void __launch_bounds__(128) pool_kernel(
    const float* __restrict__ X3, const int* __restrict__ ccsr,
    const int* __restrict__ coff, float* __restrict__ pool)
{
    int c = blockIdx.x;
    int t = threadIdx.x;
    int beg = coff[c], end = coff[c + 1];

    float4 m = make_float4(-INFINITY, -INFINITY, -INFINITY, -INFINITY);
    int i = beg;
    for (; i + 3 < end; i += 4) {
        float4 a = ((const float4*)(X3 + (long)ccsr[i] * 512))[t];
        float4 b = ((const float4*)(X3 + (long)ccsr[i + 1] * 512))[t];
        float4 c2 = ((const float4*)(X3 + (long)ccsr[i + 2] * 512))[t];
        float4 d = ((const float4*)(X3 + (long)ccsr[i + 3] * 512))[t];
        m = max4(m, max4(max4(a, b), max4(c2, d)));
    }
    for (; i < end; ++i)
        m = max4(m, ((const float4*)(X3 + (long)ccsr[i] * 512))[t]);
    if (beg == end) m = make_float4(0.f, 0.f, 0.f, 0.f);
    ((float4*)(pool + (long)c * 512))[t] = m;
}

// Column-wise normalize, coalesced
__global__ void __launch_bounds__(256) normalize_kernel(
    const float* __restrict__ pool, float* __restrict__ out, int nc)
{
    int lane  = threadIdx.x & 31;
    int phase = threadIdx.x >> 5;
    int col   = blockIdx.x * 32 + lane;

    float ss = 0.f;
    for (int r = phase; r < nc; r += 8) {
        float v = pool[(long)r * 512 + col];
        ss += v * v;
    }
    __shared__ float red[256];
    red[threadIdx.x] = ss;
    __syncthreads();
#pragma unroll
    for (int s = 128; s >= 32; s >>= 1) {
        if (threadIdx.x < s) red[threadIdx.x] += red[threadIdx.x + s];
        __syncthreads();
    }
    if (threadIdx.x < 32) red[threadIdx.x] = 1.0f / (sqrtf(red[threadIdx.x]) + 1e-6f);
    __syncthreads();
    float inv = red[lane];
    for (int r = phase; r < nc; r += 8)
        out[(long)r * 512 + col] = pool[(long)r * 512 + col] * inv;
}

// ---------------------------------------------------------------------------
static constexpr int MLP_SMEM_BYTES = (2 * 128 * 36 + 2 * 64 * 36) * 4;  // 55296

extern "C" void kernel_launch(void* const* d_in, const int* in_sizes, int n_in,
                              void* d_out, int out_size)
{
    const float* x   = (const float*)d_in[0];
    const int*   ei  = (const int*)d_in[1];
    const int*   cl  = (const int*)d_in[2];
    const float *w1_0 = (const float*)d_in[3],  *b1_0 = (const float*)d_in[4];
    const float *w2_0 = (const float*)d_in[5],  *b2_0 = (const float*)d_in[6];
    const float *w1_1 = (const float*)d_in[7],  *b1_1 = (const float*)d_in[8];
    const float *w2_1 = (const float*)d_in[9],  *b2_1 = (const float*)d_in[10];
    const float *w1_2 = (const float*)d_in[11], *b1_2 = (const float*)d_in[12];
    const float *w2_2 = (const float*)d_in[13], *b2_2 = (const float*)d_in[14];

    int n  = in_sizes[0] / 64;
    int E  = in_sizes[1] / 2;
    int nc = out_size / 512;
    const int* src = ei;
    const int* dst = ei + E;

    float* X1;   cudaGetSymbolAddress((void**)&X1, g_X1);
    float* X2;   cudaGetSymbolAddress((void**)&X2, g_X2);
    float* X3;   cudaGetSymbolAddress((void**)&X3, g_X3);
    float* pool; cudaGetSymbolAddress((void**)&pool, g_pool);
    float* tp;   cudaGetSymbolAddress((void**)&tp, g_tp);
    uint2 *pw1_1, *pw1_2, *pw2_1, *pw2_2;
    cudaGetSymbolAddress((void**)&pw1_1, g_pw1_1);
    cudaGetSymbolAddress((void**)&pw1_2, g_pw1_2);
    cudaGetSymbolAddress((void**)&pw2_1, g_pw2_1);
    cudaGetSymbolAddress((void**)&pw2_2, g_pw2_2);
    int *cnt, *off, *cur, *csr, *ccnt, *coff, *ccur, *ccsr;
    cudaGetSymbolAddress((void**)&cnt,  g_cnt);
    cudaGetSymbolAddress((void**)&off,  g_off);
    cudaGetSymbolAddress((void**)&cur,  g_cur);
    cudaGetSymbolAddress((void**)&csr,  g_csr);
    cudaGetSymbolAddress((void**)&ccnt, g_ccnt);
    cudaGetSymbolAddress((void**)&coff, g_coff);
    cudaGetSymbolAddress((void**)&ccur, g_ccur);
    cudaGetSymbolAddress((void**)&ccsr, g_ccsr);

    cudaFuncSetAttribute(mlp_mma_kernel<64, false, 0, false>,
                         cudaFuncAttributeMaxDynamicSharedMemorySize, MLP_SMEM_BYTES);
    cudaFuncSetAttribute(mlp_mma_kernel<128, true, 2, true>,
                         cudaFuncAttributeMaxDynamicSharedMemorySize, MLP_SMEM_BYTES);
    cudaFuncSetAttribute(mlp_mma_kernel<256, true, 4, true>,
                         cudaFuncAttributeMaxDynamicSharedMemorySize, MLP_SMEM_BYTES);
    cudaFuncSetAttribute(mlp_mma_head<128, true, 2>,
                         cudaFuncAttributeMaxDynamicSharedMemorySize, MLP_SMEM_BYTES);
    cudaFuncSetAttribute(mlp_mma_head<256, true, 4>,
                         cudaFuncAttributeMaxDynamicSharedMemorySize, MLP_SMEM_BYTES);

    static cudaStream_t s2 = nullptr;
    static cudaEvent_t evFork = nullptr, evCsr = nullptr;
    static cudaEvent_t ev0 = nullptr, evH1 = nullptr, ev1 = nullptr, evH2 = nullptr;
    if (!s2) {
        cudaStreamCreateWithFlags(&s2, cudaStreamNonBlocking);
        cudaEventCreateWithFlags(&evFork, cudaEventDisableTiming);
        cudaEventCreateWithFlags(&evCsr,  cudaEventDisableTiming);
        cudaEventCreateWithFlags(&ev0,    cudaEventDisableTiming);
        cudaEventCreateWithFlags(&evH1,   cudaEventDisableTiming);
        cudaEventCreateWithFlags(&ev1,    cudaEventDisableTiming);
        cudaEventCreateWithFlags(&evH2,   cudaEventDisableTiming);
    }

    int nb = (n + 127) / 128;

    // ---- side stream: weight packs, then CSR build ----
    cudaEventRecord(evFork, 0);
    cudaStreamWaitEvent(s2, evFork, 0);
    pack_w1_kernel<<<(64 * 64 + 255) / 256, 256, 0, s2>>>(w1_1, pw1_1, 128);
    pack_w2_kernel<<<(128 * 32 + 255) / 256, 256, 0, s2>>>(w2_1, pw2_1, 128);
    pack_w1_kernel<<<(128 * 64 + 255) / 256, 256, 0, s2>>>(w1_2, pw1_2, 256);
    pack_w2_kernel<<<(256 * 32 + 255) / 256, 256, 0, s2>>>(w2_2, pw2_2, 256);
    cudaMemsetAsync(cnt,  0, (size_t)n  * sizeof(int), s2);
    cudaMemsetAsync(ccnt, 0, (size_t)nc * sizeof(int), s2);
    hist_kernel<<<(E + 255) / 256, 256, 0, s2>>>(dst, cnt, E);
    hist_kernel<<<(n + 255) / 256, 256, 0, s2>>>(cl, ccnt, n);
    scan_kernel<<<1, 1024, 0, s2>>>(cnt, off, cur, n);
    scan_kernel<<<1, 1024, 0, s2>>>(ccnt, coff, ccur, nc);
    fill_edge_kernel<<<(E + 255) / 256, 256, 0, s2>>>(src, dst, cur, csr, E);
    fill_node_kernel<<<(n + 255) / 256, 256, 0, s2>>>(cl, ccur, ccsr, n);
    cudaEventRecord(evCsr, s2);

    // ---- Layer 0: 64 -> 64 (raw f32 weights) ----
    mlp_mma_kernel<64, false, 0, false><<<nb, 256, MLP_SMEM_BYTES>>>(
        x, nullptr, w1_0, b1_0, w2_0, b2_0, X1, n);
    cudaEventRecord(ev0, 0);

    // side: head of layer 1 (reads X1 h-half) overlaps agg0
    cudaStreamWaitEvent(s2, ev0, 0);
    mlp_mma_head<128, true, 2><<<nb, 256, MLP_SMEM_BYTES, s2>>>(X1, pw1_1, tp, n);
    cudaEventRecord(evH1, s2);

    cudaStreamWaitEvent(0, evCsr, 0);
    agg_kernel<64><<<((n + 1) / 2 * 32 + 255) / 256, 256>>>(X1, csr, off, n);

    // ---- Layer 1 tail: 128 -> 128 ----
    cudaStreamWaitEvent(0, evH1, 0);
    mlp_mma_kernel<128, true, 2, true><<<nb, 256, MLP_SMEM_BYTES>>>(
        X1, tp, pw1_1, b1_1, pw2_1, b2_1, X2, n);
    cudaEventRecord(ev1, 0);

    // side: head of layer 2 overlaps agg1
    cudaStreamWaitEvent(s2, ev1, 0);
    mlp_mma_head<256, true, 4><<<nb, 256, MLP_SMEM_BYTES, s2>>>(X2, pw1_2, tp, n);
    cudaEventRecord(evH2, s2);

    agg_kernel<128><<<(n * 32 + 255) / 256, 256>>>(X2, csr, off, n);

    // ---- Layer 2 tail: 256 -> 256 ----
    cudaStreamWaitEvent(0, evH2, 0);
    mlp_mma_kernel<256, true, 4, true><<<nb, 256, MLP_SMEM_BYTES>>>(
        X2, tp, pw1_2, b1_2, pw2_2, b2_2, X3, n);
    agg_kernel<256><<<(n * 32 + 255) / 256, 256>>>(X3, csr, off, n);

    // ---- Cluster pool + normalize ----
    pool_kernel<<<nc, 128>>>(X3, ccsr, coff, pool);
    normalize_kernel<<<16, 256>>>(pool, (float*)d_out, nc);
}

// round 16
// speedup vs baseline: 1.0293x; 1.0293x over previous
#include <cuda_runtime.h>
#include <cuda_bf16.h>
#include <cstdint>

// ---------------------------------------------------------------------------
// SubGraph: 3x (MLP -> gather/scatter-max -> concat) -> cluster max-pool ->
// column-wise L2 normalization.
// N=50000, E=800000, C0=64, H=64, NC=2500. Channels 64->128->256->512.
// Round 16: round-14 base (354.2us best) with side-stream reorder: CSR build
// FIRST (unblocks agg0 early), weight packs after (gated by evPack before
// the layer-1 MLP). No kernel changes.
// ---------------------------------------------------------------------------

// Static scratch (no allocations allowed)
__device__ __align__(16) float g_X1[50000 * 128];
__device__ __align__(16) float g_X2[50000 * 256];
__device__ __align__(16) float g_X3[50000 * 512];
__device__ __align__(16) float g_pool[2500 * 512];

// packed weights for layers 1/2: pw1 [K/2][64] uint2 ; pw2 [(C/64)*32][64] uint2
__device__ __align__(16) uint2 g_pw1_1[64 * 64];
__device__ __align__(16) uint2 g_pw1_2[128 * 64];
__device__ __align__(16) uint2 g_pw2_1[64 * 64];
__device__ __align__(16) uint2 g_pw2_2[128 * 64];

__device__ int g_cnt[50000];
__device__ int g_off[50001];
__device__ int g_cur[50000];
__device__ int g_csr[800000];

__device__ int g_ccnt[2500];
__device__ int g_coff[2501];
__device__ int g_ccur[2500];
__device__ int g_ccsr[50000];

__device__ __forceinline__ float4 max4(float4 a, float4 b) {
    return make_float4(fmaxf(a.x, b.x), fmaxf(a.y, b.y),
                       fmaxf(a.z, b.z), fmaxf(a.w, b.w));
}

// ---------------------------------------------------------------------------
// bf16 split helpers + mma
// ---------------------------------------------------------------------------
__device__ __forceinline__ uint2 split_pack2(float x0, float x1)
{
    __nv_bfloat16 h0 = __float2bfloat16_rn(x0);
    __nv_bfloat16 h1 = __float2bfloat16_rn(x1);
    float f0 = __bfloat162float(h0), f1 = __bfloat162float(h1);
    __nv_bfloat16 l0 = __float2bfloat16_rn(x0 - f0);
    __nv_bfloat16 l1 = __float2bfloat16_rn(x1 - f1);
    uint2 r;
    r.x = ((unsigned)__bfloat16_as_ushort(h1) << 16) | (unsigned)__bfloat16_as_ushort(h0);
    r.y = ((unsigned)__bfloat16_as_ushort(l1) << 16) | (unsigned)__bfloat16_as_ushort(l0);
    return r;
}

__device__ __forceinline__ void mma16816(float* c,
    unsigned a0, unsigned a1, unsigned a2, unsigned a3,
    unsigned b0, unsigned b1)
{
    asm volatile(
        "mma.sync.aligned.m16n8k16.row.col.f32.bf16.bf16.f32 "
        "{%0,%1,%2,%3}, {%4,%5,%6,%7}, {%8,%9}, {%0,%1,%2,%3};"
        : "+f"(c[0]), "+f"(c[1]), "+f"(c[2]), "+f"(c[3])
        : "r"(a0), "r"(a1), "r"(a2), "r"(a3), "r"(b0), "r"(b1));
}

// ---------------------------------------------------------------------------
// Weight pre-pack kernels (side stream; layers 1/2 only)
// ---------------------------------------------------------------------------
__global__ void pack_w1_kernel(const float* __restrict__ w, uint2* __restrict__ out, int K)
{
    int idx = blockIdx.x * 256 + threadIdx.x;
    if (idx >= (K / 2) * 64) return;
    int kw = idx >> 6, nn = idx & 63;
    out[idx] = split_pack2(__ldg(&w[(long)(2 * kw) * 64 + nn]),
                           __ldg(&w[(long)(2 * kw + 1) * 64 + nn]));
}

__global__ void pack_w2_kernel(const float* __restrict__ w, uint2* __restrict__ out, int C)
{
    int idx = blockIdx.x * 256 + threadIdx.x;
    if (idx >= C * 32) return;
    int cc = idx >> 11;
    int kw = (idx >> 6) & 31;
    int nn = idx & 63;
    out[idx] = split_pack2(__ldg(&w[(long)(2 * kw) * C + cc * 64 + nn]),
                           __ldg(&w[(long)(2 * kw + 1) * C + cc * 64 + nn]));
}

// ---------------------------------------------------------------------------
// CSR build
// ---------------------------------------------------------------------------
__global__ void hist_kernel(const int* __restrict__ idx, int* __restrict__ cnt, int m)
{
    int i = blockIdx.x * blockDim.x + threadIdx.x;
    if (i < m) atomicAdd(&cnt[__ldg(idx + i)], 1);
}

__global__ void scan_kernel(const int* __restrict__ cnt, int* __restrict__ off,
                            int* __restrict__ cur, int n)
{
    __shared__ int sums[1024];
    int tid = threadIdx.x;
    int chunk = (n + 1023) >> 10;
    int start = tid * chunk;
    int lim = min(start + chunk, n);
    int s = 0;
    for (int i = start; i < lim; ++i) s += cnt[i];
    sums[tid] = s;
    __syncthreads();
    for (int d = 1; d < 1024; d <<= 1) {
        int v = (tid >= d) ? sums[tid - d] : 0;
        __syncthreads();
        sums[tid] += v;
        __syncthreads();
    }
    int run = (tid == 0) ? 0 : sums[tid - 1];
    for (int i = start; i < lim; ++i) {
        off[i] = run; cur[i] = run;
        run += cnt[i];
    }
    if (tid == 1023) off[n] = sums[1023];
}

__global__ void fill_edge_kernel(const int* __restrict__ src, const int* __restrict__ dst,
                                 int* __restrict__ cur, int* __restrict__ csr, int E)
{
    int e = blockIdx.x * blockDim.x + threadIdx.x;
    if (e >= E) return;
    int pos = atomicAdd(&cur[__ldg(dst + e)], 1);
    csr[pos] = __ldg(src + e);
}

__global__ void fill_node_kernel(const int* __restrict__ cl, int* __restrict__ ccur,
                                 int* __restrict__ ccsr, int n)
{
    int i = blockIdx.x * blockDim.x + threadIdx.x;
    if (i >= n) return;
    int pos = atomicAdd(&ccur[__ldg(cl + i)], 1);
    ccsr[pos] = i;
}

// ---------------------------------------------------------------------------
// Tensor-core MLP: Y[:, :C] = relu(X[:, :C] @ w1 + b1) @ w2 + b2
// Block: 256 thr = 8 warps (4 row x 2 col), tile 128 rows x 64 cols.
// WPACK: weights pre-packed (uint2) vs raw f32 converted inline (layer 0).
// Smem: (2*128*36 + 2*64*36) words = 55296 B. 3 CTAs/SM via launch bounds.
// ---------------------------------------------------------------------------
template<int C, bool WPACK>
__global__ void __launch_bounds__(256, 3) mlp_mma_kernel(
    const float* __restrict__ X,
    const void* __restrict__ w1v, const float* __restrict__ b1,
    const void* __restrict__ w2v, const float* __restrict__ b2,
    float* __restrict__ Y, int n)
{
    constexpr int LD_OUT = 2 * C;
    constexpr int SA = 20;   // A chunk row stride (16 data words + 4 pad)
    constexpr int ST = 36;   // t row stride (32 data words + 4 pad)
    constexpr int SB = 36;   // B row stride

    extern __shared__ unsigned smem[];
    unsigned* sA_hi = smem;                    // 128*36
    unsigned* sA_lo = sA_hi + 128 * ST;        // 128*36
    unsigned* sB_hi = sA_lo + 128 * ST;        // 64*36
    unsigned* sB_lo = sB_hi + 64 * SB;         // 64*36

    const int tid = threadIdx.x;
    const int wid = tid >> 5, lane = tid & 31;
    const int g = lane >> 2, t4 = lane & 3;
    const int warpRow = wid >> 1, warpCol = wid & 1;
    const int rowBase = blockIdx.x * 128;
    const int nn = tid & 63, k0 = tid >> 6;

    float c[2][4][4];
#pragma unroll
    for (int a = 0; a < 2; ++a)
#pragma unroll
        for (int b = 0; b < 4; ++b)
#pragma unroll
            for (int d = 0; d < 4; ++d) c[a][b][d] = 0.f;

    // ---- matmul1: t = X @ w1, K chunks of 32 ----
    for (int kc = 0; kc < C / 32; ++kc) {
        __syncthreads();
        // stage A chunk: 128 rows x 16 words (bf16x2), stride SA
#pragma unroll
        for (int it = 0; it < 8; ++it) {
            int idx = tid + it * 256;
            int r = idx >> 4, kw = idx & 15;
            int row = rowBase + r;
            float2 v = make_float2(0.f, 0.f);
            if (row < n) v = *(const float2*)&X[(long)row * C + kc * 32 + kw * 2];
            uint2 p = split_pack2(v.x, v.y);
            sA_hi[r * SA + kw] = p.x; sA_lo[r * SA + kw] = p.y;
        }
        // stage B chunk
        if (WPACK) {
            const uint2* pw1 = (const uint2*)w1v;
#pragma unroll
            for (int i = 0; i < 4; ++i) {
                int kw = k0 + i * 4;
                uint2 v = __ldg(&pw1[((long)kc * 16 + kw) * 64 + nn]);
                sB_hi[nn * SB + kw] = v.x; sB_lo[nn * SB + kw] = v.y;
            }
        } else {
            const float* w1 = (const float*)w1v;
#pragma unroll
            for (int i = 0; i < 4; ++i) {
                int kw = k0 + i * 4;
                int k = kc * 32 + kw * 2;
                uint2 v = split_pack2(__ldg(&w1[(long)k * 64 + nn]),
                                      __ldg(&w1[(long)(k + 1) * 64 + nn]));
                sB_hi[nn * SB + kw] = v.x; sB_lo[nn * SB + kw] = v.y;
            }
        }
        __syncthreads();

#pragma unroll
        for (int ks = 0; ks < 2; ++ks) {
            int kw0 = ks * 8;
            unsigned ah[2][4], al[2][4];
#pragma unroll
            for (int mt = 0; mt < 2; ++mt) {
                int r0 = warpRow * 32 + mt * 16;
                ah[mt][0] = sA_hi[(r0 + g) * SA + kw0 + t4];
                ah[mt][1] = sA_hi[(r0 + g + 8) * SA + kw0 + t4];
                ah[mt][2] = sA_hi[(r0 + g) * SA + kw0 + 4 + t4];
                ah[mt][3] = sA_hi[(r0 + g + 8) * SA + kw0 + 4 + t4];
                al[mt][0] = sA_lo[(r0 + g) * SA + kw0 + t4];
                al[mt][1] = sA_lo[(r0 + g + 8) * SA + kw0 + t4];
                al[mt][2] = sA_lo[(r0 + g) * SA + kw0 + 4 + t4];
                al[mt][3] = sA_lo[(r0 + g + 8) * SA + kw0 + 4 + t4];
            }
#pragma unroll
            for (int nt = 0; nt < 4; ++nt) {
                int nb_ = warpCol * 32 + nt * 8;
                unsigned bh0 = sB_hi[(nb_ + g) * SB + kw0 + t4];
                unsigned bh1 = sB_hi[(nb_ + g) * SB + kw0 + 4 + t4];
                unsigned bl0 = sB_lo[(nb_ + g) * SB + kw0 + t4];
                unsigned bl1 = sB_lo[(nb_ + g) * SB + kw0 + 4 + t4];
#pragma unroll
                for (int mt = 0; mt < 2; ++mt) {
                    mma16816(c[mt][nt], ah[mt][0], ah[mt][1], ah[mt][2], ah[mt][3], bh0, bh1);
                    mma16816(c[mt][nt], ah[mt][0], ah[mt][1], ah[mt][2], ah[mt][3], bl0, bl1);
                    mma16816(c[mt][nt], al[mt][0], al[mt][1], al[mt][2], al[mt][3], bh0, bh1);
                }
            }
        }
    }

    __syncthreads();   // all A/B reads done; safe to overwrite as t

    // ---- bias + relu; repack t (bf16 hi/lo) into sA with stride ST ----
#pragma unroll
    for (int mt = 0; mt < 2; ++mt) {
#pragma unroll
        for (int nt = 0; nt < 4; ++nt) {
            int j = warpCol * 32 + nt * 8 + t4 * 2;
            float2 bb = *(const float2*)&b1[j];
            float v0 = fmaxf(c[mt][nt][0] + bb.x, 0.f);
            float v1 = fmaxf(c[mt][nt][1] + bb.y, 0.f);
            float v2 = fmaxf(c[mt][nt][2] + bb.x, 0.f);
            float v3 = fmaxf(c[mt][nt][3] + bb.y, 0.f);
            int r0 = warpRow * 32 + mt * 16 + g;
            int wc = warpCol * 16 + nt * 4 + t4;
            uint2 p0 = split_pack2(v0, v1);
            sA_hi[r0 * ST + wc] = p0.x; sA_lo[r0 * ST + wc] = p0.y;
            uint2 p1 = split_pack2(v2, v3);
            sA_hi[(r0 + 8) * ST + wc] = p1.x; sA_lo[(r0 + 8) * ST + wc] = p1.y;
        }
    }

    // ---- matmul2: Y = t @ w2 + b2, 64-col output slices ----
    for (int cc = 0; cc < C / 64; ++cc) {
        __syncthreads();
        if (WPACK) {
            const uint2* pw2 = (const uint2*)w2v;
#pragma unroll
            for (int i = 0; i < 8; ++i) {
                int kw = k0 + i * 4;
                uint2 v = __ldg(&pw2[((long)cc * 32 + kw) * 64 + nn]);
                sB_hi[nn * SB + kw] = v.x; sB_lo[nn * SB + kw] = v.y;
            }
        } else {
            const float* w2 = (const float*)w2v;
#pragma unroll
            for (int i = 0; i < 8; ++i) {
                int kw = k0 + i * 4;
                int k = kw * 2;
                uint2 v = split_pack2(__ldg(&w2[(long)k * C + cc * 64 + nn]),
                                      __ldg(&w2[(long)(k + 1) * C + cc * 64 + nn]));
                sB_hi[nn * SB + kw] = v.x; sB_lo[nn * SB + kw] = v.y;
            }
        }
        __syncthreads();

        float c2[2][4][4];
#pragma unroll
        for (int a = 0; a < 2; ++a)
#pragma unroll
            for (int b = 0; b < 4; ++b)
#pragma unroll
                for (int d = 0; d < 4; ++d) c2[a][b][d] = 0.f;

#pragma unroll
        for (int ks = 0; ks < 4; ++ks) {
            int kw0 = ks * 8;
            unsigned ah[2][4], al[2][4];
#pragma unroll
            for (int mt = 0; mt < 2; ++mt) {
                int r0 = warpRow * 32 + mt * 16;
                ah[mt][0] = sA_hi[(r0 + g) * ST + kw0 + t4];
                ah[mt][1] = sA_hi[(r0 + g + 8) * ST + kw0 + t4];
                ah[mt][2] = sA_hi[(r0 + g) * ST + kw0 + 4 + t4];
                ah[mt][3] = sA_hi[(r0 + g + 8) * ST + kw0 + 4 + t4];
                al[mt][0] = sA_lo[(r0 + g) * ST + kw0 + t4];
                al[mt][1] = sA_lo[(r0 + g + 8) * ST + kw0 + t4];
                al[mt][2] = sA_lo[(r0 + g) * ST + kw0 + 4 + t4];
                al[mt][3] = sA_lo[(r0 + g + 8) * ST + kw0 + 4 + t4];
            }
#pragma unroll
            for (int nt = 0; nt < 4; ++nt) {
                int nb_ = warpCol * 32 + nt * 8;
                unsigned bh0 = sB_hi[(nb_ + g) * SB + kw0 + t4];
                unsigned bh1 = sB_hi[(nb_ + g) * SB + kw0 + 4 + t4];
                unsigned bl0 = sB_lo[(nb_ + g) * SB + kw0 + t4];
                unsigned bl1 = sB_lo[(nb_ + g) * SB + kw0 + 4 + t4];
#pragma unroll
                for (int mt = 0; mt < 2; ++mt) {
                    mma16816(c2[mt][nt], ah[mt][0], ah[mt][1], ah[mt][2], ah[mt][3], bh0, bh1);
                    mma16816(c2[mt][nt], ah[mt][0], ah[mt][1], ah[mt][2], ah[mt][3], bl0, bl1);
                    mma16816(c2[mt][nt], al[mt][0], al[mt][1], al[mt][2], al[mt][3], bh0, bh1);
                }
            }
        }

        // + b2, store f32 to Y
#pragma unroll
        for (int mt = 0; mt < 2; ++mt) {
#pragma unroll
            for (int nt = 0; nt < 4; ++nt) {
                int j = cc * 64 + warpCol * 32 + nt * 8 + t4 * 2;
                float2 bb = *(const float2*)&b2[j];
                int r0 = rowBase + warpRow * 32 + mt * 16 + g;
                if (r0 < n)
                    *(float2*)&Y[(long)r0 * LD_OUT + j] =
                        make_float2(c2[mt][nt][0] + bb.x, c2[mt][nt][1] + bb.y);
                if (r0 + 8 < n)
                    *(float2*)&Y[(long)(r0 + 8) * LD_OUT + j] =
                        make_float2(c2[mt][nt][2] + bb.x, c2[mt][nt][3] + bb.y);
            }
        }
    }
}

// ---------------------------------------------------------------------------
// CSR gather-max aggregation: aggr[node] = max over in-edges of h[src]; 0 if none.
// ---------------------------------------------------------------------------
template<int C>
__global__ void __launch_bounds__(256) agg_kernel(
    float* __restrict__ Xn,
    const int* __restrict__ csr, const int* __restrict__ off, int n)
{
    constexpr int LD  = 2 * C;
    constexpr int V   = C / 4;
    constexpr int LPE = (V < 32) ? V : 32;
    constexpr int EPW = 32 / LPE;
    constexpr int NV  = V / LPE;

    int gwarp = (int)((blockIdx.x * 256u + threadIdx.x) >> 5);
    int lane  = threadIdx.x & 31;
    int node  = gwarp * EPW + (EPW > 1 ? lane / LPE : 0);
    if (node >= n) return;
    int li = lane % LPE;

    int beg = off[node], end = off[node + 1];

    float4 m[NV];
#pragma unroll
    for (int v = 0; v < NV; ++v)
        m[v] = make_float4(-INFINITY, -INFINITY, -INFINITY, -INFINITY);

    int e = beg;
    for (; e + 3 < end; e += 4) {
        int s0 = __ldg(csr + e), s1 = __ldg(csr + e + 1);
        int s2 = __ldg(csr + e + 2), s3 = __ldg(csr + e + 3);
        const float4* h0 = (const float4*)(Xn + (long)s0 * LD) + li;
        const float4* h1 = (const float4*)(Xn + (long)s1 * LD) + li;
        const float4* h2 = (const float4*)(Xn + (long)s2 * LD) + li;
        const float4* h3 = (const float4*)(Xn + (long)s3 * LD) + li;
#pragma unroll
        for (int v = 0; v < NV; ++v) {
            float4 a = h0[v * LPE];
            float4 b = h1[v * LPE];
            float4 c = h2[v * LPE];
            float4 d = h3[v * LPE];
            m[v] = max4(m[v], max4(max4(a, b), max4(c, d)));
        }
    }
    for (; e < end; ++e) {
        const float4* h0 = (const float4*)(Xn + (long)__ldg(csr + e) * LD) + li;
#pragma unroll
        for (int v = 0; v < NV; ++v)
            m[v] = max4(m[v], h0[v * LPE]);
    }

    float4* ap = (float4*)(Xn + (long)node * LD + C);
    if (beg == end) {
#pragma unroll
        for (int v = 0; v < NV; ++v)
            ap[li + v * LPE] = make_float4(0.f, 0.f, 0.f, 0.f);
    } else {
#pragma unroll
        for (int v = 0; v < NV; ++v)
            ap[li + v * LPE] = m[v];
    }
}

// ---------------------------------------------------------------------------
// Cluster max-pool via CSR
// ---------------------------------------------------------------------------
__global__ void __launch_bounds__(128) pool_kernel(
    const float* __restrict__ X3, const int* __restrict__ ccsr,
    const int* __restrict__ coff, float* __restrict__ pool)
{
    int c = blockIdx.x;
    int t = threadIdx.x;
    int beg = coff[c], end = coff[c + 1];

    float4 m = make_float4(-INFINITY, -INFINITY, -INFINITY, -INFINITY);
    int i = beg;
    for (; i + 3 < end; i += 4) {
        float4 a = ((const float4*)(X3 + (long)ccsr[i] * 512))[t];
        float4 b = ((const float4*)(X3 + (long)ccsr[i + 1] * 512))[t];
        float4 c2 = ((const float4*)(X3 + (long)ccsr[i + 2] * 512))[t];
        float4 d = ((const float4*)(X3 + (long)ccsr[i + 3] * 512))[t];
        m = max4(m, max4(max4(a, b), max4(c2, d)));
    }
    for (; i < end; ++i)
        m = max4(m, ((const float4*)(X3 + (long)ccsr[i] * 512))[t]);
    if (beg == end) m = make_float4(0.f, 0.f, 0.f, 0.f);
    ((float4*)(pool + (long)c * 512))[t] = m;
}

// Column-wise normalize, coalesced
__global__ void __launch_bounds__(256) normalize_kernel(
    const float* __restrict__ pool, float* __restrict__ out, int nc)
{
    int lane  = threadIdx.x & 31;
    int phase = threadIdx.x >> 5;
    int col   = blockIdx.x * 32 + lane;

    float ss = 0.f;
    for (int r = phase; r < nc; r += 8) {
        float v = pool[(long)r * 512 + col];
        ss += v * v;
    }
    __shared__ float red[256];
    red[threadIdx.x] = ss;
    __syncthreads();
#pragma unroll
    for (int s = 128; s >= 32; s >>= 1) {
        if (threadIdx.x < s) red[threadIdx.x] += red[threadIdx.x + s];
        __syncthreads();
    }
    if (threadIdx.x < 32) red[threadIdx.x] = 1.0f / (sqrtf(red[threadIdx.x]) + 1e-6f);
    __syncthreads();
    float inv = red[lane];
    for (int r = phase; r < nc; r += 8)
        out[(long)r * 512 + col] = pool[(long)r * 512 + col] * inv;
}

// ---------------------------------------------------------------------------
static constexpr int MLP_SMEM_BYTES = (2 * 128 * 36 + 2 * 64 * 36) * 4;  // 55296

extern "C" void kernel_launch(void* const* d_in, const int* in_sizes, int n_in,
                              void* d_out, int out_size)
{
    const float* x   = (const float*)d_in[0];
    const int*   ei  = (const int*)d_in[1];
    const int*   cl  = (const int*)d_in[2];
    const float *w1_0 = (const float*)d_in[3],  *b1_0 = (const float*)d_in[4];
    const float *w2_0 = (const float*)d_in[5],  *b2_0 = (const float*)d_in[6];
    const float *w1_1 = (const float*)d_in[7],  *b1_1 = (const float*)d_in[8];
    const float *w2_1 = (const float*)d_in[9],  *b2_1 = (const float*)d_in[10];
    const float *w1_2 = (const float*)d_in[11], *b1_2 = (const float*)d_in[12];
    const float *w2_2 = (const float*)d_in[13], *b2_2 = (const float*)d_in[14];

    int n  = in_sizes[0] / 64;
    int E  = in_sizes[1] / 2;
    int nc = out_size / 512;
    const int* src = ei;
    const int* dst = ei + E;

    float* X1;   cudaGetSymbolAddress((void**)&X1, g_X1);
    float* X2;   cudaGetSymbolAddress((void**)&X2, g_X2);
    float* X3;   cudaGetSymbolAddress((void**)&X3, g_X3);
    float* pool; cudaGetSymbolAddress((void**)&pool, g_pool);
    uint2 *pw1_1, *pw1_2, *pw2_1, *pw2_2;
    cudaGetSymbolAddress((void**)&pw1_1, g_pw1_1);
    cudaGetSymbolAddress((void**)&pw1_2, g_pw1_2);
    cudaGetSymbolAddress((void**)&pw2_1, g_pw2_1);
    cudaGetSymbolAddress((void**)&pw2_2, g_pw2_2);
    int *cnt, *off, *cur, *csr, *ccnt, *coff, *ccur, *ccsr;
    cudaGetSymbolAddress((void**)&cnt,  g_cnt);
    cudaGetSymbolAddress((void**)&off,  g_off);
    cudaGetSymbolAddress((void**)&cur,  g_cur);
    cudaGetSymbolAddress((void**)&csr,  g_csr);
    cudaGetSymbolAddress((void**)&ccnt, g_ccnt);
    cudaGetSymbolAddress((void**)&coff, g_coff);
    cudaGetSymbolAddress((void**)&ccur, g_ccur);
    cudaGetSymbolAddress((void**)&ccsr, g_ccsr);

    cudaFuncSetAttribute(mlp_mma_kernel<64, false>,
                         cudaFuncAttributeMaxDynamicSharedMemorySize, MLP_SMEM_BYTES);
    cudaFuncSetAttribute(mlp_mma_kernel<128, true>,
                         cudaFuncAttributeMaxDynamicSharedMemorySize, MLP_SMEM_BYTES);
    cudaFuncSetAttribute(mlp_mma_kernel<256, true>,
                         cudaFuncAttributeMaxDynamicSharedMemorySize, MLP_SMEM_BYTES);

    // One side stream; three events (fork, csr-done, packs-done).
    static cudaStream_t s2 = nullptr;
    static cudaEvent_t evFork = nullptr, evCsr = nullptr, evPack = nullptr;
    if (!s2) {
        cudaStreamCreateWithFlags(&s2, cudaStreamNonBlocking);
        cudaEventCreateWithFlags(&evFork, cudaEventDisableTiming);
        cudaEventCreateWithFlags(&evCsr,  cudaEventDisableTiming);
        cudaEventCreateWithFlags(&evPack, cudaEventDisableTiming);
    }

    // ---- side stream: CSR build FIRST (unblocks agg0), then weight packs ----
    cudaEventRecord(evFork, 0);
    cudaStreamWaitEvent(s2, evFork, 0);
    cudaMemsetAsync(cnt,  0, (size_t)n  * sizeof(int), s2);
    cudaMemsetAsync(ccnt, 0, (size_t)nc * sizeof(int), s2);
    hist_kernel<<<(E + 255) / 256, 256, 0, s2>>>(dst, cnt, E);
    hist_kernel<<<(n + 255) / 256, 256, 0, s2>>>(cl, ccnt, n);
    scan_kernel<<<1, 1024, 0, s2>>>(cnt, off, cur, n);
    scan_kernel<<<1, 1024, 0, s2>>>(ccnt, coff, ccur, nc);
    fill_edge_kernel<<<(E + 255) / 256, 256, 0, s2>>>(src, dst, cur, csr, E);
    fill_node_kernel<<<(n + 255) / 256, 256, 0, s2>>>(cl, ccur, ccsr, n);
    cudaEventRecord(evCsr, s2);
    pack_w1_kernel<<<(64 * 64 + 255) / 256, 256, 0, s2>>>(w1_1, pw1_1, 128);
    pack_w2_kernel<<<(128 * 32 + 255) / 256, 256, 0, s2>>>(w2_1, pw2_1, 128);
    pack_w1_kernel<<<(128 * 64 + 255) / 256, 256, 0, s2>>>(w1_2, pw1_2, 256);
    pack_w2_kernel<<<(256 * 32 + 255) / 256, 256, 0, s2>>>(w2_2, pw2_2, 256);
    cudaEventRecord(evPack, s2);

    int nb = (n + 127) / 128;

    // ---- Layer 0: 64 -> 64 (raw f32 weights, converted inline) ----
    mlp_mma_kernel<64, false><<<nb, 256, MLP_SMEM_BYTES>>>(
        x, w1_0, b1_0, w2_0, b2_0, X1, n);
    cudaStreamWaitEvent(0, evCsr, 0);
    agg_kernel<64><<<((n + 1) / 2 * 32 + 255) / 256, 256>>>(X1, csr, off, n);

    // ---- Layer 1: 128 -> 128 (pre-packed weights; gate on packs done) ----
    cudaStreamWaitEvent(0, evPack, 0);
    mlp_mma_kernel<128, true><<<nb, 256, MLP_SMEM_BYTES>>>(
        X1, pw1_1, b1_1, pw2_1, b2_1, X2, n);
    agg_kernel<128><<<(n * 32 + 255) / 256, 256>>>(X2, csr, off, n);

    // ---- Layer 2: 256 -> 256 (pre-packed weights) ----
    mlp_mma_kernel<256, true><<<nb, 256, MLP_SMEM_BYTES>>>(
        X2, pw1_2, b1_2, pw2_2, b2_2, X3, n);
    agg_kernel<256><<<(n * 32 + 255) / 256, 256>>>(X3, csr, off, n);

    // ---- Cluster pool + normalize ----
    pool_kernel<<<nc, 128>>>(X3, ccsr, coff, pool);
    normalize_kernel<<<16, 256>>>(pool, (float*)d_out, nc);
}